// round 15
// baseline (speedup 1.0000x reference)
#include <cuda_runtime.h>
#include <cuda_fp16.h>
#include <mma.h>
#include <math.h>
#include <stdint.h>

using namespace nvcuda;

#define Bb   2
#define Lseq 1024
#define Hdim 1024
#define NHn  16
#define Dd   64
#define HDd  1024          // NH * D
#define Mtot (Bb*Lseq)     // 2048

// ---------------- scratch (device globals; no allocations allowed) ----------
__device__ float g_q[Bb*Lseq*HDd];
__device__ float g_k[Bb*Lseq*HDd];
__device__ float g_v[Bb*Lseq*HDd];
__device__ float g_alpha[Bb*Lseq*NHn];
__device__ float g_beta[Bb*Lseq*NHn];
__device__ float g_y[Bb*Lseq*HDd];   // scan output, [B,NH,L,D] contiguous
__device__ float g_z[Bb*Lseq*HDd];   // after conv residual, [B,L,HD]
__device__ float g_s[Mtot];          // per-row max |z|
__device__ float g_is[Mtot];         // 1 / g_s

// ===========================================================================
// Double-buffered WMMA GEMM core pieces.
// Tile: 128 rows x 32 k-halves, row stride RSTRH=40 halves (80B).
// Stage = 4 tiles (Ah, Al, Wh, Wl) = 20480 halves = 40960 B; 2 stages dynamic.
// ===========================================================================
#define RSTRH 40
#define TILEH 5120            // halves per tile
#define STGH  20480           // halves per stage
#define GSMEM (2 * STGH * 2)  // bytes = 81920

__device__ __forceinline__ void cvt_pack(const float* v, uint32_t* hw,
                                         uint32_t* lw)
{
#pragma unroll
    for (int j = 0; j < 8; j++) {
        float x0 = v[2 * j], x1 = v[2 * j + 1];
        __half h0 = __float2half_rn(x0), h1 = __float2half_rn(x1);
        __half l0 = __float2half_rn(x0 - __half2float(h0));
        __half l1 = __float2half_rn(x1 - __half2float(h1));
        hw[j] = (uint32_t)__half_as_ushort(h0)
              | ((uint32_t)__half_as_ushort(h1) << 16);
        lw[j] = (uint32_t)__half_as_ushort(l0)
              | ((uint32_t)__half_as_ushort(l1) << 16);
    }
}

// ---------------------------------------------------------------------------
// QKV GEMM: C = A @ W^T (bias added by bias_kernel).  Double-buffered.
// ---------------------------------------------------------------------------
__global__ void __launch_bounds__(256)
gemm_wmma(const float* __restrict__ A,
          const float* __restrict__ W0f, const float* __restrict__ W1f,
          const float* __restrict__ W2f,
          float* __restrict__ C0, float* __restrict__ C1,
          float* __restrict__ C2)
{
    extern __shared__ __half dsm[];

    const int z = blockIdx.z;
    const float* Wf = (z == 0) ? W0f : (z == 1) ? W1f : W2f;
    float* C        = (z == 0) ? C0 : (z == 1) ? C1 : C2;

    const int tid = threadIdx.x;
    const int wid = tid >> 5;
    const int wm = wid & 3, wn = wid >> 2;
    const int m0 = blockIdx.y * 128, n0 = blockIdx.x * 128;

    wmma::fragment<wmma::accumulator, 16, 16, 16, float> acc[2][4];
#pragma unroll
    for (int mt = 0; mt < 2; mt++)
#pragma unroll
        for (int nt = 0; nt < 4; nt++)
            wmma::fill_fragment(acc[mt][nt], 0.0f);

    const int row = tid >> 1;
    const int hh  = tid & 1;
    const float* Ap = A  + (size_t)(m0 + row) * 1024 + hh * 16;
    const float* Wp = Wf + (size_t)(n0 + row) * 1024 + hh * 16;
    const uint32_t hoff = (uint32_t)(row * RSTRH + hh * 16);  // halves

    float av[16], wv[16];
#pragma unroll
    for (int j = 0; j < 4; j++) {
        float4 fa = *(const float4*)(Ap + j * 4);
        float4 fw = *(const float4*)(Wp + j * 4);
        av[j * 4 + 0] = fa.x; av[j * 4 + 1] = fa.y;
        av[j * 4 + 2] = fa.z; av[j * 4 + 3] = fa.w;
        wv[j * 4 + 0] = fw.x * 1024.0f; wv[j * 4 + 1] = fw.y * 1024.0f;
        wv[j * 4 + 2] = fw.z * 1024.0f; wv[j * 4 + 3] = fw.w * 1024.0f;
    }
    {   // store chunk 0 into stage 0
        uint32_t hw[8], lw[8];
        cvt_pack(av, hw, lw);
        *(uint4*)(dsm + 0 * TILEH + hoff)     = make_uint4(hw[0], hw[1], hw[2], hw[3]);
        *(uint4*)(dsm + 0 * TILEH + hoff + 8) = make_uint4(hw[4], hw[5], hw[6], hw[7]);
        *(uint4*)(dsm + 1 * TILEH + hoff)     = make_uint4(lw[0], lw[1], lw[2], lw[3]);
        *(uint4*)(dsm + 1 * TILEH + hoff + 8) = make_uint4(lw[4], lw[5], lw[6], lw[7]);
        cvt_pack(wv, hw, lw);
        *(uint4*)(dsm + 2 * TILEH + hoff)     = make_uint4(hw[0], hw[1], hw[2], hw[3]);
        *(uint4*)(dsm + 2 * TILEH + hoff + 8) = make_uint4(hw[4], hw[5], hw[6], hw[7]);
        *(uint4*)(dsm + 3 * TILEH + hoff)     = make_uint4(lw[0], lw[1], lw[2], lw[3]);
        *(uint4*)(dsm + 3 * TILEH + hoff + 8) = make_uint4(lw[4], lw[5], lw[6], lw[7]);
    }
    __syncthreads();

    for (int i = 0; i < 32; i++) {
        const int cur = i & 1, nxt = cur ^ 1;
        // issue next chunk's global loads (latency hidden behind wmma below)
        if (i + 1 < 32) {
            int k0 = (i + 1) * 32;
#pragma unroll
            for (int j = 0; j < 4; j++) {
                float4 fa = *(const float4*)(Ap + k0 + j * 4);
                float4 fw = *(const float4*)(Wp + k0 + j * 4);
                av[j * 4 + 0] = fa.x; av[j * 4 + 1] = fa.y;
                av[j * 4 + 2] = fa.z; av[j * 4 + 3] = fa.w;
                wv[j * 4 + 0] = fw.x * 1024.0f; wv[j * 4 + 1] = fw.y * 1024.0f;
                wv[j * 4 + 2] = fw.z * 1024.0f; wv[j * 4 + 3] = fw.w * 1024.0f;
            }
        }
        // compute current stage
        const __half* sAh = dsm + cur * STGH + 0 * TILEH;
        const __half* sAl = dsm + cur * STGH + 1 * TILEH;
        const __half* sWh = dsm + cur * STGH + 2 * TILEH;
        const __half* sWl = dsm + cur * STGH + 3 * TILEH;
#pragma unroll
        for (int ks = 0; ks < 2; ks++) {
            wmma::fragment<wmma::matrix_a, 16, 16, 16, __half, wmma::row_major>
                fah[2], fal[2];
#pragma unroll
            for (int mt = 0; mt < 2; mt++) {
                wmma::load_matrix_sync(fah[mt],
                    sAh + (wm * 32 + mt * 16) * RSTRH + ks * 16, RSTRH);
                wmma::load_matrix_sync(fal[mt],
                    sAl + (wm * 32 + mt * 16) * RSTRH + ks * 16, RSTRH);
            }
#pragma unroll
            for (int nt = 0; nt < 4; nt++) {
                wmma::fragment<wmma::matrix_b, 16, 16, 16, __half,
                               wmma::col_major> fbh, fbl;
                wmma::load_matrix_sync(fbh,
                    sWh + (wn * 64 + nt * 16) * RSTRH + ks * 16, RSTRH);
                wmma::load_matrix_sync(fbl,
                    sWl + (wn * 64 + nt * 16) * RSTRH + ks * 16, RSTRH);
#pragma unroll
                for (int mt = 0; mt < 2; mt++) {
                    wmma::mma_sync(acc[mt][nt], fah[mt], fbh, acc[mt][nt]);
                    wmma::mma_sync(acc[mt][nt], fal[mt], fbh, acc[mt][nt]);
                    wmma::mma_sync(acc[mt][nt], fah[mt], fbl, acc[mt][nt]);
                }
            }
        }
        // convert + store next stage
        if (i + 1 < 32) {
            __half* nAh = dsm + nxt * STGH + 0 * TILEH;
            __half* nAl = dsm + nxt * STGH + 1 * TILEH;
            __half* nWh = dsm + nxt * STGH + 2 * TILEH;
            __half* nWl = dsm + nxt * STGH + 3 * TILEH;
            uint32_t hw[8], lw[8];
            cvt_pack(av, hw, lw);
            *(uint4*)(nAh + hoff)     = make_uint4(hw[0], hw[1], hw[2], hw[3]);
            *(uint4*)(nAh + hoff + 8) = make_uint4(hw[4], hw[5], hw[6], hw[7]);
            *(uint4*)(nAl + hoff)     = make_uint4(lw[0], lw[1], lw[2], lw[3]);
            *(uint4*)(nAl + hoff + 8) = make_uint4(lw[4], lw[5], lw[6], lw[7]);
            cvt_pack(wv, hw, lw);
            *(uint4*)(nWh + hoff)     = make_uint4(hw[0], hw[1], hw[2], hw[3]);
            *(uint4*)(nWh + hoff + 8) = make_uint4(hw[4], hw[5], hw[6], hw[7]);
            *(uint4*)(nWl + hoff)     = make_uint4(lw[0], lw[1], lw[2], lw[3]);
            *(uint4*)(nWl + hoff + 8) = make_uint4(lw[4], lw[5], lw[6], lw[7]);
        }
        __syncthreads();
    }

    const float S = 1.0f / 1024.0f;
#pragma unroll
    for (int mt = 0; mt < 2; mt++) {
#pragma unroll
        for (int nt = 0; nt < 4; nt++) {
#pragma unroll
            for (int e = 0; e < acc[mt][nt].num_elements; e++)
                acc[mt][nt].x[e] *= S;
            float* cp = C + (size_t)(m0 + wm * 32 + mt * 16) * 1024
                          + (n0 + wn * 64 + nt * 16);
            wmma::store_matrix_sync(cp, acc[mt][nt], 1024, wmma::mem_row_major);
        }
    }
}

// ---------------------------------------------------------------------------
// Out-proj GEMM with per-row input scaling.  Same double-buffered structure.
// ---------------------------------------------------------------------------
__global__ void __launch_bounds__(256)
gemm_wmma_rs(const float* __restrict__ A, const float* __restrict__ Wf,
             float* __restrict__ C, const float* __restrict__ inv_s)
{
    extern __shared__ __half dsm[];

    const int tid = threadIdx.x;
    const int wid = tid >> 5;
    const int wm = wid & 3, wn = wid >> 2;
    const int m0 = blockIdx.y * 128, n0 = blockIdx.x * 128;

    wmma::fragment<wmma::accumulator, 16, 16, 16, float> acc[2][4];
#pragma unroll
    for (int mt = 0; mt < 2; mt++)
#pragma unroll
        for (int nt = 0; nt < 4; nt++)
            wmma::fill_fragment(acc[mt][nt], 0.0f);

    const int row = tid >> 1;
    const int hh  = tid & 1;
    const float isr = inv_s[m0 + row];
    const float* Ap = A  + (size_t)(m0 + row) * 1024 + hh * 16;
    const float* Wp = Wf + (size_t)(n0 + row) * 1024 + hh * 16;
    const uint32_t hoff = (uint32_t)(row * RSTRH + hh * 16);

    float av[16], wv[16];
#pragma unroll
    for (int j = 0; j < 4; j++) {
        float4 fa = *(const float4*)(Ap + j * 4);
        float4 fw = *(const float4*)(Wp + j * 4);
        av[j * 4 + 0] = fa.x * isr; av[j * 4 + 1] = fa.y * isr;
        av[j * 4 + 2] = fa.z * isr; av[j * 4 + 3] = fa.w * isr;
        wv[j * 4 + 0] = fw.x * 1024.0f; wv[j * 4 + 1] = fw.y * 1024.0f;
        wv[j * 4 + 2] = fw.z * 1024.0f; wv[j * 4 + 3] = fw.w * 1024.0f;
    }
    {
        uint32_t hw[8], lw[8];
        cvt_pack(av, hw, lw);
        *(uint4*)(dsm + 0 * TILEH + hoff)     = make_uint4(hw[0], hw[1], hw[2], hw[3]);
        *(uint4*)(dsm + 0 * TILEH + hoff + 8) = make_uint4(hw[4], hw[5], hw[6], hw[7]);
        *(uint4*)(dsm + 1 * TILEH + hoff)     = make_uint4(lw[0], lw[1], lw[2], lw[3]);
        *(uint4*)(dsm + 1 * TILEH + hoff + 8) = make_uint4(lw[4], lw[5], lw[6], lw[7]);
        cvt_pack(wv, hw, lw);
        *(uint4*)(dsm + 2 * TILEH + hoff)     = make_uint4(hw[0], hw[1], hw[2], hw[3]);
        *(uint4*)(dsm + 2 * TILEH + hoff + 8) = make_uint4(hw[4], hw[5], hw[6], hw[7]);
        *(uint4*)(dsm + 3 * TILEH + hoff)     = make_uint4(lw[0], lw[1], lw[2], lw[3]);
        *(uint4*)(dsm + 3 * TILEH + hoff + 8) = make_uint4(lw[4], lw[5], lw[6], lw[7]);
    }
    __syncthreads();

    for (int i = 0; i < 32; i++) {
        const int cur = i & 1, nxt = cur ^ 1;
        if (i + 1 < 32) {
            int k0 = (i + 1) * 32;
#pragma unroll
            for (int j = 0; j < 4; j++) {
                float4 fa = *(const float4*)(Ap + k0 + j * 4);
                float4 fw = *(const float4*)(Wp + k0 + j * 4);
                av[j * 4 + 0] = fa.x * isr; av[j * 4 + 1] = fa.y * isr;
                av[j * 4 + 2] = fa.z * isr; av[j * 4 + 3] = fa.w * isr;
                wv[j * 4 + 0] = fw.x * 1024.0f; wv[j * 4 + 1] = fw.y * 1024.0f;
                wv[j * 4 + 2] = fw.z * 1024.0f; wv[j * 4 + 3] = fw.w * 1024.0f;
            }
        }
        const __half* sAh = dsm + cur * STGH + 0 * TILEH;
        const __half* sAl = dsm + cur * STGH + 1 * TILEH;
        const __half* sWh = dsm + cur * STGH + 2 * TILEH;
        const __half* sWl = dsm + cur * STGH + 3 * TILEH;
#pragma unroll
        for (int ks = 0; ks < 2; ks++) {
            wmma::fragment<wmma::matrix_a, 16, 16, 16, __half, wmma::row_major>
                fah[2], fal[2];
#pragma unroll
            for (int mt = 0; mt < 2; mt++) {
                wmma::load_matrix_sync(fah[mt],
                    sAh + (wm * 32 + mt * 16) * RSTRH + ks * 16, RSTRH);
                wmma::load_matrix_sync(fal[mt],
                    sAl + (wm * 32 + mt * 16) * RSTRH + ks * 16, RSTRH);
            }
#pragma unroll
            for (int nt = 0; nt < 4; nt++) {
                wmma::fragment<wmma::matrix_b, 16, 16, 16, __half,
                               wmma::col_major> fbh, fbl;
                wmma::load_matrix_sync(fbh,
                    sWh + (wn * 64 + nt * 16) * RSTRH + ks * 16, RSTRH);
                wmma::load_matrix_sync(fbl,
                    sWl + (wn * 64 + nt * 16) * RSTRH + ks * 16, RSTRH);
#pragma unroll
                for (int mt = 0; mt < 2; mt++) {
                    wmma::mma_sync(acc[mt][nt], fah[mt], fbh, acc[mt][nt]);
                    wmma::mma_sync(acc[mt][nt], fal[mt], fbh, acc[mt][nt]);
                    wmma::mma_sync(acc[mt][nt], fah[mt], fbl, acc[mt][nt]);
                }
            }
        }
        if (i + 1 < 32) {
            __half* nAh = dsm + nxt * STGH + 0 * TILEH;
            __half* nAl = dsm + nxt * STGH + 1 * TILEH;
            __half* nWh = dsm + nxt * STGH + 2 * TILEH;
            __half* nWl = dsm + nxt * STGH + 3 * TILEH;
            uint32_t hw[8], lw[8];
            cvt_pack(av, hw, lw);
            *(uint4*)(nAh + hoff)     = make_uint4(hw[0], hw[1], hw[2], hw[3]);
            *(uint4*)(nAh + hoff + 8) = make_uint4(hw[4], hw[5], hw[6], hw[7]);
            *(uint4*)(nAl + hoff)     = make_uint4(lw[0], lw[1], lw[2], lw[3]);
            *(uint4*)(nAl + hoff + 8) = make_uint4(lw[4], lw[5], lw[6], lw[7]);
            cvt_pack(wv, hw, lw);
            *(uint4*)(nWh + hoff)     = make_uint4(hw[0], hw[1], hw[2], hw[3]);
            *(uint4*)(nWh + hoff + 8) = make_uint4(hw[4], hw[5], hw[6], hw[7]);
            *(uint4*)(nWl + hoff)     = make_uint4(lw[0], lw[1], lw[2], lw[3]);
            *(uint4*)(nWl + hoff + 8) = make_uint4(lw[4], lw[5], lw[6], lw[7]);
        }
        __syncthreads();
    }

#pragma unroll
    for (int mt = 0; mt < 2; mt++) {
#pragma unroll
        for (int nt = 0; nt < 4; nt++) {
            float* cp = C + (size_t)(m0 + wm * 32 + mt * 16) * 1024
                          + (n0 + wn * 64 + nt * 16);
            wmma::store_matrix_sync(cp, acc[mt][nt], 1024, wmma::mem_row_major);
        }
    }
}

// ---------------------------------------------------------------------------
// Per-row max |z| and reciprocal.   (proven)
// ---------------------------------------------------------------------------
__global__ __launch_bounds__(256)
void rowmax_kernel(const float* __restrict__ z,
                   float* __restrict__ s, float* __restrict__ is)
{
    int m = blockIdx.x * 8 + (threadIdx.x >> 5);
    int lane = threadIdx.x & 31;
    const float* row = z + (size_t)m * 1024;
    float mx = 0.f;
    for (int j = lane; j < 1024; j += 32) mx = fmaxf(mx, fabsf(row[j]));
#pragma unroll
    for (int o = 16; o; o >>= 1)
        mx = fmaxf(mx, __shfl_xor_sync(0xFFFFFFFFu, mx, o));
    if (lane == 0) {
        mx = fmaxf(mx, 1e-30f);
        s[m] = mx;
        is[m] = 1.0f / mx;
    }
}

// ---------------------------------------------------------------------------
// Bias add (QKV): C[m, n] += bias[n].   (proven)
// ---------------------------------------------------------------------------
__global__ __launch_bounds__(256)
void bias_kernel(float* __restrict__ C0, float* __restrict__ C1,
                 float* __restrict__ C2,
                 const float* __restrict__ b0, const float* __restrict__ b1,
                 const float* __restrict__ b2)
{
    const int z = blockIdx.z;
    float* C       = (z == 0) ? C0 : (z == 1) ? C1 : C2;
    const float* b = (z == 0) ? b0 : (z == 1) ? b1 : b2;
    int idx = blockIdx.x * 256 + threadIdx.x;
    C[idx] += b[idx & 1023];
}

// Bias + per-row rescale (out-proj): out = C*(s[m]/1024) + bias[n].  (proven)
__global__ __launch_bounds__(256)
void bias_scale_kernel(float* __restrict__ C, const float* __restrict__ s,
                       const float* __restrict__ bias)
{
    int idx = blockIdx.x * 256 + threadIdx.x;
    int m = idx >> 10, n = idx & 1023;
    C[idx] = C[idx] * (s[m] * (1.0f / 1024.0f)) + bias[n];
}

// ---------------------------------------------------------------------------
// alpha = sigmoid(X @ Wa^T), beta = softplus(X @ Wb^T).   (proven)
// ---------------------------------------------------------------------------
__global__ __launch_bounds__(256)
void ab_kernel(const float* __restrict__ X,
               const float* __restrict__ Wa, const float* __restrict__ Wb,
               float* __restrict__ alpha, float* __restrict__ beta)
{
    __shared__ float sW[32][65];
    __shared__ float sX[8][64];
    const int tid = threadIdx.x;
    const int r = tid >> 5, cc = tid & 31;
    const int m0 = blockIdx.x * 8;
    float acc = 0.f;

    for (int k0 = 0; k0 < 1024; k0 += 64) {
        __syncthreads();
        for (int idx = tid; idx < 32 * 64; idx += 256) {
            int row = idx >> 6, kk = idx & 63;
            const float* src = (row < 16) ? (Wa + row * 1024)
                                          : (Wb + (row - 16) * 1024);
            sW[row][kk] = src[k0 + kk];
        }
        for (int idx = tid; idx < 8 * 64; idx += 256) {
            int rr = idx >> 6, kk = idx & 63;
            sX[rr][kk] = X[(size_t)(m0 + rr) * 1024 + k0 + kk];
        }
        __syncthreads();
#pragma unroll 8
        for (int kk = 0; kk < 64; kk++)
            acc = fmaf(sX[r][kk], sW[cc][kk], acc);
    }

    int m = m0 + r;
    if (cc < 16) {
        alpha[m * NHn + cc] = 1.f / (1.f + expf(-acc));
    } else {
        float sp = (acc > 20.f) ? acc : log1pf(expf(acc));
        beta[m * NHn + (cc - 16)] = sp;
    }
}

// ---------------------------------------------------------------------------
// Gated delta recurrence v4 (PROVEN round 14): vectorized smem, concurrent
// reductions, o via exact identity.
// ---------------------------------------------------------------------------
#define SCAN_T 32
__global__ __launch_bounds__(128)
void scan_kernel(const float* __restrict__ qb, const float* __restrict__ kb,
                 const float* __restrict__ vb, const float* __restrict__ ab,
                 const float* __restrict__ bbet, float* __restrict__ yb)
{
    const int blk = blockIdx.x;           // b*64 + h*4 + rg
    const int rg = blk & 3;
    const int h  = (blk >> 2) & 15;
    const int b  = blk >> 6;
    const int tid = threadIdx.x;
    const int rl = tid >> 3;              // row within group 0..15
    const int c  = tid & 7;               // chunk
    const int cb = c * 8;

    float S[8] = {0.f,0.f,0.f,0.f,0.f,0.f,0.f,0.f};

    __shared__ __align__(16) float sk[SCAN_T][64];
    __shared__ __align__(16) float sq[SCAN_T][64];
    __shared__ __align__(16) float sv[SCAN_T][16];
    __shared__ float sa[SCAN_T];
    __shared__ float sbv[SCAN_T];
    __shared__ float sp[SCAN_T];

    const size_t baseqk = (size_t)b * Lseq * HDd + h * 64;
    const size_t basev  = baseqk + rg * 16;
    const size_t baseab = (size_t)b * Lseq * NHn + h;
    float* yout = yb + ((size_t)(b * NHn + h) * Lseq) * Dd + rg * 16;

    for (int t0 = 0; t0 < Lseq; t0 += SCAN_T) {
        __syncthreads();
#pragma unroll
        for (int it = 0; it < 4; it++) {
            int idx = tid + it * 128;          // 0..511
            int t = idx >> 4, e = (idx & 15) * 4;
            size_t g = baseqk + (size_t)(t0 + t) * HDd + e;
            *(float4*)&sk[t][e] = *(const float4*)(kb + g);
            *(float4*)&sq[t][e] = *(const float4*)(qb + g);
        }
        {
            int t = tid >> 2, e = (tid & 3) * 4;
            *(float4*)&sv[t][e] =
                *(const float4*)(vb + basev + (size_t)(t0 + t) * HDd + e);
        }
        if (tid < SCAN_T)
            sa[tid] = ab[baseab + (size_t)(t0 + tid) * NHn];
        else if (tid < 2 * SCAN_T)
            sbv[tid - SCAN_T] = bbet[baseab + (size_t)(t0 + tid - SCAN_T) * NHn];
        __syncthreads();

        {
            int t = tid >> 2;
            int part = tid & 3;
            float pp = 0.f;
#pragma unroll
            for (int j4 = 0; j4 < 4; j4++) {
                float4 kf = *(float4*)&sk[t][part * 16 + j4 * 4];
                float4 qf = *(float4*)&sq[t][part * 16 + j4 * 4];
                pp = fmaf(kf.x, qf.x, pp);
                pp = fmaf(kf.y, qf.y, pp);
                pp = fmaf(kf.z, qf.z, pp);
                pp = fmaf(kf.w, qf.w, pp);
            }
            pp += __shfl_xor_sync(0xFFFFFFFFu, pp, 1);
            pp += __shfl_xor_sync(0xFFFFFFFFu, pp, 2);
            if (part == 0) sp[t] = pp;
        }
        __syncthreads();

        for (int t = 0; t < SCAN_T; t++) {
            float kr[8], qr[8];
            {
                float4 k0v = *(float4*)&sk[t][cb];
                float4 k1v = *(float4*)&sk[t][cb + 4];
                kr[0] = k0v.x; kr[1] = k0v.y; kr[2] = k0v.z; kr[3] = k0v.w;
                kr[4] = k1v.x; kr[5] = k1v.y; kr[6] = k1v.z; kr[7] = k1v.w;
                float4 q0v = *(float4*)&sq[t][cb];
                float4 q1v = *(float4*)&sq[t][cb + 4];
                qr[0] = q0v.x; qr[1] = q0v.y; qr[2] = q0v.z; qr[3] = q0v.w;
                qr[4] = q1v.x; qr[5] = q1v.y; qr[6] = q1v.z; qr[7] = q1v.w;
            }
            float u0 = 0.f, u1 = 0.f, x0 = 0.f, x1 = 0.f;
#pragma unroll
            for (int i = 0; i < 8; i += 2) {
                u0 = fmaf(S[i],     kr[i],     u0);
                u1 = fmaf(S[i + 1], kr[i + 1], u1);
                x0 = fmaf(S[i],     qr[i],     x0);
                x1 = fmaf(S[i + 1], qr[i + 1], x1);
            }
            float u  = u0 + u1;
            float uq = x0 + x1;
            u  += __shfl_xor_sync(0xFFFFFFFFu, u, 1);
            uq += __shfl_xor_sync(0xFFFFFFFFu, uq, 1);
            u  += __shfl_xor_sync(0xFFFFFFFFu, u, 2);
            uq += __shfl_xor_sync(0xFFFFFFFFu, uq, 2);
            u  += __shfl_xor_sync(0xFFFFFFFFu, u, 4);
            uq += __shfl_xor_sync(0xFFFFFFFFu, uq, 4);

            const float a  = sa[t];
            const float bt = sbv[t];
            const float vv = sv[t][rl];
            const float w  = bt * (vv - a * u);

#pragma unroll
            for (int i = 0; i < 8; i += 2) {
                S[i]     = fmaf(a, S[i],     w * kr[i]);
                S[i + 1] = fmaf(a, S[i + 1], w * kr[i + 1]);
            }
            if (c == 0) {
                float o = fmaf(a, uq, w * sp[t]);
                yout[(size_t)(t0 + t) * Dd + rl] = o;
            }
        }
    }
}

// ---------------------------------------------------------------------------
// Residual depthwise causal conv (proven, fp32 out).
// ---------------------------------------------------------------------------
__global__ __launch_bounds__(256)
void conv_kernel(const float* __restrict__ y, const float* __restrict__ Wc,
                 float* __restrict__ z)
{
    int idx = blockIdx.x * 256 + threadIdx.x;
    int cch = idx & (HDd - 1);
    int l   = (idx >> 10) & (Lseq - 1);
    float4 w = *(const float4*)(Wc + cch * 4);
    float acc = y[idx];
    if (l >= 3) acc = fmaf(w.x, y[idx - 3 * HDd], acc);
    if (l >= 2) acc = fmaf(w.y, y[idx - 2 * HDd], acc);
    if (l >= 1) acc = fmaf(w.z, y[idx - 1 * HDd], acc);
    acc = fmaf(w.w, y[idx], acc);
    z[idx] = acc;
}

// ---------------------------------------------------------------------------
extern "C" void kernel_launch(void* const* d_in, const int* in_sizes, int n_in,
                              void* d_out, int out_size)
{
    const float* hs = (const float*)d_in[0];
    const float* Wq = (const float*)d_in[1];
    const float* bq = (const float*)d_in[2];
    const float* Wk = (const float*)d_in[3];
    const float* bk = (const float*)d_in[4];
    const float* Wv = (const float*)d_in[5];
    const float* bv = (const float*)d_in[6];
    const float* Wa = (const float*)d_in[7];
    const float* Wb = (const float*)d_in[8];
    const float* Wc = (const float*)d_in[9];
    const float* Wo = (const float*)d_in[10];
    const float* bo = (const float*)d_in[11];
    float* out = (float*)d_out;

    float *pq, *pk, *pv, *pa, *pb, *py, *pz, *ps, *pis;
    cudaGetSymbolAddress((void**)&pq, g_q);
    cudaGetSymbolAddress((void**)&pk, g_k);
    cudaGetSymbolAddress((void**)&pv, g_v);
    cudaGetSymbolAddress((void**)&pa, g_alpha);
    cudaGetSymbolAddress((void**)&pb, g_beta);
    cudaGetSymbolAddress((void**)&py, g_y);
    cudaGetSymbolAddress((void**)&pz, g_z);
    cudaGetSymbolAddress((void**)&ps, g_s);
    cudaGetSymbolAddress((void**)&pis, g_is);

    cudaFuncSetAttribute(gemm_wmma,
                         cudaFuncAttributeMaxDynamicSharedMemorySize, GSMEM);
    cudaFuncSetAttribute(gemm_wmma_rs,
                         cudaFuncAttributeMaxDynamicSharedMemorySize, GSMEM);

    // 1) fused QKV projections (tensor cores, fp16-split, double-buffered)
    dim3 gqkv(8, 16, 3);
    gemm_wmma<<<gqkv, 256, GSMEM>>>(hs, Wq, Wk, Wv, pq, pk, pv);
    dim3 gb(Mtot * 1024 / 256, 1, 3);
    bias_kernel<<<gb, 256>>>(pq, pk, pv, bq, bk, bv);

    // 2) alpha / beta gates
    ab_kernel<<<Mtot / 8, 256>>>(hs, Wa, Wb, pa, pb);

    // 3) sequential gated-delta scan (v4)
    scan_kernel<<<Bb * NHn * 4, 128>>>(pq, pk, pv, pa, pb, py);

    // 4) residual depthwise causal conv (fp32)
    conv_kernel<<<(Bb * Lseq * HDd) / 256, 256>>>(py, Wc, pz);

    // 5) output projection: per-row dynamic scaling -> fp16-split wmma
    rowmax_kernel<<<Mtot / 8, 256>>>(pz, ps, pis);
    dim3 gout(8, 16, 1);
    gemm_wmma_rs<<<gout, 256, GSMEM>>>(pz, Wo, out, pis);
    bias_scale_kernel<<<Mtot * 1024 / 256, 256>>>(out, ps, bo);
}